// round 9
// baseline (speedup 1.0000x reference)
#include <cuda_runtime.h>
#include <math.h>

#define BATCH 128
#define CHN   3
#define IMH   135
#define IMW   240
#define NCH   (BATCH * CHN)
#define EPSV  1e-10f

typedef unsigned long long u64;

// ---------------- packed f32x2 helpers (sm_103a) ---------------------------
__device__ __forceinline__ u64 pk(float lo, float hi) {
    u64 r; asm("mov.b64 %0, {%1,%2};" : "=l"(r) : "f"(lo), "f"(hi)); return r;
}
__device__ __forceinline__ void upk(u64 v, float& lo, float& hi) {
    asm("mov.b64 {%0,%1}, %2;" : "=f"(lo), "=f"(hi) : "l"(v));
}
__device__ __forceinline__ u64 fma2(u64 a, u64 b, u64 c) {
    u64 d; asm("fma.rn.f32x2 %0, %1, %2, %3;" : "=l"(d) : "l"(a), "l"(b), "l"(c)); return d;
}
__device__ __forceinline__ u64 mul2(u64 a, u64 b) {
    u64 d; asm("mul.rn.f32x2 %0, %1, %2;" : "=l"(d) : "l"(a), "l"(b)); return d;
}
__device__ __forceinline__ u64 add2(u64 a, u64 b) {
    u64 d; asm("add.rn.f32x2 %0, %1, %2;" : "=l"(d) : "l"(a), "l"(b)); return d;
}
// (a.hi, b.lo) — odd-tap pair from two neighboring even pairs
__device__ __forceinline__ u64 mid(u64 a, u64 b) {
    float al, ah, bl, bh; upk(a, al, ah); upk(b, bl, bh); return pk(ah, bl);
}

// ---------------- scratch (device globals — no allocation) ----------------
__device__ float g_num[NCH];
__device__ float g_den[NCH];
__device__ float g_dot[BATCH];
__device__ float g_w1[4][9];   // scalar weights; symmetric half j=0..(N-1)/2

// ---------------- init: zero accumulators + weights every launch -----------
__global__ void init_kernel() {
    int i = threadIdx.x;
    if (i < NCH)   { g_num[i] = 0.0f; g_den[i] = 0.0f; }
    if (i < BATCH) { g_dot[i] = 0.0f; }
    if (i == 0) {
        const int Ns[4] = {17, 9, 5, 3};
        for (int s = 0; s < 4; s++) {
            int n = Ns[s];
            float sigma  = (float)n / 5.0f;
            float inv2s2 = 1.0f / (2.0f * sigma * sigma);
            float wv[17];
            float sum = 0.0f;
            for (int j = 0; j < n; j++) {
                float d = (float)(j - n / 2);
                float v = expf(-d * d * inv2s2);
                wv[j] = v;
                sum += v;
            }
            float is = 1.0f / sum;
            for (int j = 0; j < (n + 1) / 2; j++)
                g_w1[s][j] = wv[j] * is;
        }
    }
}

// ---------------- fused separable VIF scale kernel -------------------------
// 256 threads = 16 lanes (2 adjacent x outputs each) x 16 y-groups, KY=2.
// All conv quantities packed by x-pair (f32x2). Scalar weights, packed on
// the fly (saves registers -> occupancy).
template <int N, int MINB, int SIDX>
__global__ __launch_bounds__(256, MINB)
void vif_scale(const float* __restrict__ R, const float* __restrict__ P) {
    constexpr int KY = 2;
    constexpr int TY = 16 * KY;          // 32
    constexpr int IH = TY + N - 1;
    constexpr int IW = 32 + N - 1;       // even (N odd) -> LDS.64 aligned
    constexpr int HO = IMH - N + 1;
    constexpr int WO = IMW - N + 1;
    constexpr int HLF = (N - 1) / 2;
    constexpr int NH = (N + 1) / 2;
    constexpr int SMB = 8 * IH * IW + 640 * IH;   // inputs + 5 packed planes
    static_assert(SMB <= 49152, "static smem limit");

    __shared__ __align__(16) char SM[SMB];
    float*      s_r = (float*)SM;
    float*      s_p = s_r + IH * IW;
    ulonglong2* hA  = (ulonglong2*)(SM + 8 * IH * IW);  // (hr2, hp2)
    ulonglong2* hB  = hA + IH * 16;                     // (hrr2, hpp2)
    u64*        hC  = (u64*)(hB + IH * 16);             // hrp2
    float*      red = (float*)SM;  // aliases inputs — dead after horizontal

    const int tid  = threadIdx.x;
    const int lane = tid & 15;
    const int yg   = tid >> 4;
    const int ch   = blockIdx.z;
    const int ox0  = blockIdx.x * 32;
    const int oy0  = blockIdx.y * TY;

    float ws[NH];
    #pragma unroll
    for (int j = 0; j < NH; j++) ws[j] = g_w1[SIDX][j];

    // ---- load tile (zero-fill outside image; invalid outputs masked) ----
    const float* __restrict__ r = R + (size_t)ch * (IMH * IMW);
    const float* __restrict__ p = P + (size_t)ch * (IMH * IMW);
    for (int idx = tid; idx < IH * IW; idx += 256) {
        int iy = idx / IW, ix = idx - iy * IW;
        int gy = oy0 + iy, gx = ox0 + ix;
        float rv = 0.0f, pv = 0.0f;
        if (gy < IMH && gx < IMW) {
            int o = gy * IMW + gx;
            rv = r[o]; pv = p[o];
        }
        s_r[idx] = rv; s_p[idx] = pv;
    }
    __syncthreads();

    // ---- horizontal pass: 5 packed windowed sums for 2 adjacent outputs ----
    for (int row = yg; row < IH; row += 16) {
        const int base = row * IW + 2 * lane;   // even -> LDS.64 aligned
        u64 ar = 0, ap = 0, arr = 0, app = 0, arp = 0;
        u64 rl = *(const u64*)&s_r[base];
        u64 pl = *(const u64*)&s_p[base];
        {   // tap 0
            u64 w  = pk(ws[0], ws[0]);
            u64 tr = mul2(w, rl), tp = mul2(w, pl);
            ar = add2(ar, tr); ap = add2(ap, tp);
            arr = fma2(tr, rl, arr); app = fma2(tp, pl, app); arp = fma2(tr, pl, arp);
        }
        #pragma unroll
        for (int j2 = 2; j2 < N; j2 += 2) {
            u64 rn = *(const u64*)&s_r[base + j2];
            u64 pn = *(const u64*)&s_p[base + j2];
            {   // even tap j2
                float wsc = ws[(j2 <= HLF) ? j2 : (N - 1 - j2)];
                u64 w  = pk(wsc, wsc);
                u64 tr = mul2(w, rn), tp = mul2(w, pn);
                ar = add2(ar, tr); ap = add2(ap, tp);
                arr = fma2(tr, rn, arr); app = fma2(tp, pn, app); arp = fma2(tr, pn, arp);
            }
            {   // odd tap j2-1, pair built from neighbor halves
                int jm = j2 - 1;
                float wsc = ws[(jm <= HLF) ? jm : (N - 1 - jm)];
                u64 w  = pk(wsc, wsc);
                u64 rm = mid(rl, rn), pm = mid(pl, pn);
                u64 tr = mul2(w, rm), tp = mul2(w, pm);
                ar = add2(ar, tr); ap = add2(ap, tp);
                arr = fma2(tr, rm, arr); app = fma2(tp, pm, app); arp = fma2(tr, pm, arp);
            }
            rl = rn; pl = pn;
        }
        hA[row * 16 + lane] = make_ulonglong2(ar, ap);
        hB[row * 16 + lane] = make_ulonglong2(arr, app);
        hC[row * 16 + lane] = arp;
    }
    __syncthreads();

    // ---- vertical pass: KY=2 packed output-rows per thread ----
    const int y0 = yg * KY;
    u64 am1[KY], am2[KY], vrr[KY], vpp[KY], vrp[KY];
    #pragma unroll
    for (int k = 0; k < KY; k++) { am1[k] = 0; am2[k] = 0; vrr[k] = 0; vpp[k] = 0; vrp[k] = 0; }

    #pragma unroll
    for (int t = 0; t < KY + N - 1; t++) {
        int row = y0 + t;
        ulonglong2 A = hA[row * 16 + lane];
        ulonglong2 B = hB[row * 16 + lane];
        u64        C = hC[row * 16 + lane];
        #pragma unroll
        for (int k = 0; k < KY; k++) {
            int j = t - k;
            if (j >= 0 && j < N) {           // static in unrolled loops
                float wsc = ws[(j <= HLF) ? j : (N - 1 - j)];
                u64 w = pk(wsc, wsc);
                am1[k] = fma2(w, A.x, am1[k]);
                am2[k] = fma2(w, A.y, am2[k]);
                vrr[k] = fma2(w, B.x, vrr[k]);
                vpp[k] = fma2(w, B.y, vpp[k]);
                vrp[k] = fma2(w, C,   vrp[k]);
            }
        }
    }

    // ---- pointwise (collapsed mask logic; lg2 — log10 cancels in ratio) ----
    float numa = 0.0f, dena = 0.0f;
    const int oxb = ox0 + 2 * lane;
    #pragma unroll
    for (int k = 0; k < KY; k++) {
        if (oy0 + y0 + k >= HO) continue;
        float m1[2], m2[2], rr[2], pp[2], rp[2];
        upk(am1[k], m1[0], m1[1]);
        upk(am2[k], m2[0], m2[1]);
        upk(vrr[k], rr[0], rr[1]);
        upk(vpp[k], pp[0], pp[1]);
        upk(vrp[k], rp[0], rp[1]);
        #pragma unroll
        for (int c = 0; c < 2; c++) {
            if (oxb + c >= WO) continue;
            float sGT = fmaxf(rr[c] - m1[c] * m1[c], 0.0f);
            float sP  = fmaxf(pp[c] - m2[c] * m2[c], 0.0f);
            float sGP = rp[c] - m1[c] * m2[c];
            // num != 0 only when all reference masks are un-triggered:
            bool cond = (sGT >= EPSV) && (sP >= EPSV) && (sGP > 0.0f);
            float g  = cond ? __fdividef(sGP, sGT + EPSV) : 0.0f;
            float sv = fmaxf(sP - g * sGP, EPSV);
            numa += __log2f(fmaf(g * g, __fdividef(sGT, sv + 2.0f), 1.0f));
            // den: sGT<EPS -> 1+sGT/2 rounds to 1.0f -> log = 0, same as masked
            dena += __log2f(fmaf(sGT, 0.5f, 1.0f));
        }
    }

    // ---- reduction -> per-channel atomics ----
    #pragma unroll
    for (int o = 16; o > 0; o >>= 1) {
        numa += __shfl_down_sync(0xFFFFFFFFu, numa, o);
        dena += __shfl_down_sync(0xFFFFFFFFu, dena, o);
    }
    if ((tid & 31) == 0) {
        red[tid >> 5]       = numa;
        red[8 + (tid >> 5)] = dena;
    }
    __syncthreads();
    if (tid == 0) {
        float n = 0.f, d = 0.f;
        #pragma unroll
        for (int w = 0; w < 8; w++) { n += red[w]; d += red[8 + w]; }
        atomicAdd(&g_num[ch], n);
        atomicAdd(&g_den[ch], d);
    }
}

// ---------------- prediction term: per-image dot((x - r), W) ---------------
__global__ __launch_bounds__(1024)
void pred_kernel(const float* __restrict__ R, const float* __restrict__ X,
                 const float* __restrict__ Wl) {
    const int img = blockIdx.x;
    const int n4  = (CHN * IMH * IMW) / 4;  // 24300
    const float4* r4 = (const float4*)(R + (size_t)img * (CHN * IMH * IMW));
    const float4* x4 = (const float4*)(X + (size_t)img * (CHN * IMH * IMW));
    const float4* w4 = (const float4*)Wl;
    float acc = 0.0f;
    for (int i = threadIdx.x; i < n4; i += 1024) {
        float4 a = x4[i], b = r4[i], w = w4[i];
        acc = fmaf(a.x - b.x, w.x, acc);
        acc = fmaf(a.y - b.y, w.y, acc);
        acc = fmaf(a.z - b.z, w.z, acc);
        acc = fmaf(a.w - b.w, w.w, acc);
    }
    __shared__ float red[32];
    #pragma unroll
    for (int o = 16; o > 0; o >>= 1)
        acc += __shfl_down_sync(0xFFFFFFFFu, acc, o);
    if ((threadIdx.x & 31) == 0) red[threadIdx.x >> 5] = acc;
    __syncthreads();
    if (threadIdx.x < 32) {
        float v = red[threadIdx.x];
        #pragma unroll
        for (int o = 16; o > 0; o >>= 1)
            v += __shfl_down_sync(0xFFFFFFFFu, v, o);
        if (threadIdx.x == 0) g_dot[img] = v;
    }
}

// ---------------- final: assemble the 3 scalars ----------------------------
__global__ void final_kernel(float* __restrict__ out) {
    const int t = threadIdx.x;  // 128 threads, one per image
    float vif = 0.0f;
    #pragma unroll
    for (int c = 0; c < CHN; c++) {
        int ch = t * CHN + c;
        vif += g_num[ch] / g_den[ch];
    }
    vif *= (1.0f / CHN);
    float rl = 1.0f - vif;
    float d  = g_dot[t];
    float pl = d * d;

    __shared__ float red[8];
    #pragma unroll
    for (int o = 16; o > 0; o >>= 1) {
        rl += __shfl_down_sync(0xFFFFFFFFu, rl, o);
        pl += __shfl_down_sync(0xFFFFFFFFu, pl, o);
    }
    if ((t & 31) == 0) {
        red[t >> 5]       = rl;
        red[4 + (t >> 5)] = pl;
    }
    __syncthreads();
    if (t == 0) {
        float rls = 0.f, pls = 0.f;
        #pragma unroll
        for (int w = 0; w < 4; w++) { rls += red[w]; pls += red[4 + w]; }
        rls *= (1.0f / BATCH);
        pls *= (1.0f / BATCH);
        out[0] = pls + rls;  // loss
        out[1] = rls;        // recons_loss
        out[2] = pls;        // prediction_loss
    }
}

// ---------------- launch ---------------------------------------------------
extern "C" void kernel_launch(void* const* d_in, const int* in_sizes, int n_in,
                              void* d_out, int out_size) {
    const float* recons = (const float*)d_in[0];
    const float* x      = (const float*)d_in[1];
    const float* Wl     = (const float*)d_in[2];
    // d_in[3] = b, cancels exactly in (pred_orig - pred_recons)
    float* out = (float*)d_out;

    init_kernel<<<1, 384>>>();

    dim3 blk(256);
    // scale 1: N=17, out 119x224, TY=32 -> grid 7x4   (smem 49152, 4 blk/SM)
    vif_scale<17, 4, 0><<<dim3(7, 4, NCH), blk>>>(recons, x);
    // scale 2: N=9,  out 127x232, TY=32 -> grid 8x4   (smem 38400, 5 blk/SM)
    vif_scale< 9, 5, 1><<<dim3(8, 4, NCH), blk>>>(recons, x);
    // scale 3: N=5,  out 131x236, TY=32 -> grid 8x5   (smem 33408, 6 blk/SM)
    vif_scale< 5, 6, 2><<<dim3(8, 5, NCH), blk>>>(recons, x);
    // scale 4: N=3,  out 133x238, TY=32 -> grid 8x5   (smem 31008, 6 blk/SM)
    vif_scale< 3, 6, 3><<<dim3(8, 5, NCH), blk>>>(recons, x);

    pred_kernel<<<BATCH, 1024>>>(recons, x, Wl);
    final_kernel<<<1, 128>>>(out);
}

// round 10
// speedup vs baseline: 1.0180x; 1.0180x over previous
#include <cuda_runtime.h>
#include <math.h>

#define BATCH 128
#define CHN   3
#define IMH   135
#define IMW   240
#define NCH   (BATCH * CHN)
#define EPSV  1e-10f

typedef unsigned long long u64;

// ---------------- packed f32x2 helpers (sm_103a) ---------------------------
__device__ __forceinline__ u64 pk(float lo, float hi) {
    u64 r; asm("mov.b64 %0, {%1,%2};" : "=l"(r) : "f"(lo), "f"(hi)); return r;
}
__device__ __forceinline__ void upk(u64 v, float& lo, float& hi) {
    asm("mov.b64 {%0,%1}, %2;" : "=f"(lo), "=f"(hi) : "l"(v));
}
__device__ __forceinline__ u64 fma2(u64 a, u64 b, u64 c) {
    u64 d; asm("fma.rn.f32x2 %0, %1, %2, %3;" : "=l"(d) : "l"(a), "l"(b), "l"(c)); return d;
}
__device__ __forceinline__ u64 mul2(u64 a, u64 b) {
    u64 d; asm("mul.rn.f32x2 %0, %1, %2;" : "=l"(d) : "l"(a), "l"(b)); return d;
}
__device__ __forceinline__ u64 add2(u64 a, u64 b) {
    u64 d; asm("add.rn.f32x2 %0, %1, %2;" : "=l"(d) : "l"(a), "l"(b)); return d;
}
// (a.hi, b.lo) — odd-tap pair from two neighboring even pairs
__device__ __forceinline__ u64 mid(u64 a, u64 b) {
    float al, ah, bl, bh; upk(a, al, ah); upk(b, bl, bh); return pk(ah, bl);
}

// ---------------- scratch (device globals — no allocation) ----------------
__device__ float g_num[NCH];
__device__ float g_den[NCH];
__device__ float g_dot[BATCH];
__device__ float g_w1[4][9];   // scalar weights; symmetric half j=0..(N-1)/2

// ---------------- init: zero accumulators + weights every launch -----------
__global__ void init_kernel() {
    int i = threadIdx.x;
    if (i < NCH)   { g_num[i] = 0.0f; g_den[i] = 0.0f; }
    if (i < BATCH) { g_dot[i] = 0.0f; }
    if (i == 0) {
        const int Ns[4] = {17, 9, 5, 3};
        for (int s = 0; s < 4; s++) {
            int n = Ns[s];
            float sigma  = (float)n / 5.0f;
            float inv2s2 = 1.0f / (2.0f * sigma * sigma);
            float wv[17];
            float sum = 0.0f;
            for (int j = 0; j < n; j++) {
                float d = (float)(j - n / 2);
                float v = expf(-d * d * inv2s2);
                wv[j] = v;
                sum += v;
            }
            float is = 1.0f / sum;
            for (int j = 0; j < (n + 1) / 2; j++)
                g_w1[s][j] = wv[j] * is;
        }
    }
}

// ---------------- ring-buffer full-height VIF scale kernel -----------------
// One block = one 64-output-wide column strip of one channel-image, marching
// down all 135 rows in 8-row groups. Horizontal results live in a minimal
// ring of 8*(LAG+1) rows in smem — NO y-halo recompute anywhere.
// 256 threads = 32 pair-lanes (2 adjacent x outputs, f32x2) x 8 rows.
template <int N, int LAG, int SIDX>
__global__ __launch_bounds__(256)
void vif_scale(const float* __restrict__ R, const float* __restrict__ P) {
    constexpr int GR  = LAG + 1;       // groups resident in ring
    constexpr int RR  = 8 * GR;        // ring rows
    constexpr int IW  = N + 63;        // strip input width (even: N odd)
    constexpr int IWH = IW / 2;        // input pairs per row
    constexpr int GIN = (IMH + 7) / 8; // 17 input groups
    constexpr int HO  = IMH - N + 1;
    constexpr int WO  = IMW - N + 1;
    constexpr int NITER = LAG + (HO + 7) / 8;
    constexpr int HLF = (N - 1) / 2;
    constexpr int NH  = (N + 1) / 2;

    __shared__ __align__(16) ulonglong2 hA[RR * 32];   // (hr, hp)
    __shared__ __align__(16) ulonglong2 hB[RR * 32];   // (hrr, hpp)
    __shared__ __align__(16) u64        hC[RR * 32];   // hrp
    __shared__ __align__(16) float      s_in[2 * 8 * IW];
    __shared__ float red[16];
    static_assert(sizeof(ulonglong2) * RR * 32 * 2 + 8 * RR * 32 +
                  2 * 8 * IW * 4 + 64 <= 49152, "smem");

    float* s_r = s_in;
    float* s_p = s_in + 8 * IW;

    const int tid  = threadIdx.x;
    const int pair = tid & 31;
    const int rloc = tid >> 5;          // row-in-group / out-row-in-group
    const int ch   = blockIdx.y;
    const int x0   = blockIdx.x * 64;

    // weights: scalar halves -> pre-packed (w,w) registers, once
    float ws[NH];
    #pragma unroll
    for (int j = 0; j < NH; j++) ws[j] = g_w1[SIDX][j];
    u64 ww2[NH];
    #pragma unroll
    for (int j = 0; j < NH; j++) ww2[j] = pk(ws[j], ws[j]);

    const float* __restrict__ r = R + (size_t)ch * (IMH * IMW);
    const float* __restrict__ p = P + (size_t)ch * (IMH * IMW);

    float numa = 0.0f, dena = 0.0f;
    int sw = 0;   // ring slot being written this iter
    int sv = 0;   // ring slot of the vertical group

    for (int i = 0; i < NITER; i++) {
        // ---- stage 8 input rows (group i) into smem ----
        if (i < GIN) {
            const int gy0 = i * 8;
            #pragma unroll
            for (int q = tid; q < 8 * IWH; q += 256) {
                int row = q / IWH;
                int c2  = q - row * IWH;
                int gy  = gy0 + row;
                int gx  = x0 + 2 * c2;
                u64 rv = 0ull, pv = 0ull;
                if (gy < IMH && gx < IMW) {
                    int o = gy * IMW + gx;
                    rv = *(const u64*)&r[o];
                    pv = *(const u64*)&p[o];
                }
                *(u64*)&s_r[row * IW + 2 * c2] = rv;
                *(u64*)&s_p[row * IW + 2 * c2] = pv;
            }
        }
        __syncthreads();

        // ---- horizontal pass: this thread's (row, pair) -> ring slot sw ----
        if (i < GIN) {
            const int base = rloc * IW + 2 * pair;
            u64 ar = 0, ap = 0, arr = 0, app = 0, arp = 0;
            u64 rl = *(const u64*)&s_r[base];
            u64 pl = *(const u64*)&s_p[base];
            {   // tap 0
                u64 w  = ww2[0];
                u64 tr = mul2(w, rl), tp = mul2(w, pl);
                ar = add2(ar, tr); ap = add2(ap, tp);
                arr = fma2(tr, rl, arr); app = fma2(tp, pl, app); arp = fma2(tr, pl, arp);
            }
            #pragma unroll
            for (int j2 = 2; j2 < N; j2 += 2) {
                u64 rn = *(const u64*)&s_r[base + j2];
                u64 pn = *(const u64*)&s_p[base + j2];
                {   // even tap j2
                    u64 w  = ww2[(j2 <= HLF) ? j2 : (N - 1 - j2)];
                    u64 tr = mul2(w, rn), tp = mul2(w, pn);
                    ar = add2(ar, tr); ap = add2(ap, tp);
                    arr = fma2(tr, rn, arr); app = fma2(tp, pn, app); arp = fma2(tr, pn, arp);
                }
                {   // odd tap j2-1 via neighbor halves
                    constexpr int JM_DUMMY = 0; (void)JM_DUMMY;
                    int jm = j2 - 1;
                    u64 w  = ww2[(jm <= HLF) ? jm : (N - 1 - jm)];
                    u64 rm = mid(rl, rn), pm = mid(pl, pn);
                    u64 tr = mul2(w, rm), tp = mul2(w, pm);
                    ar = add2(ar, tr); ap = add2(ap, tp);
                    arr = fma2(tr, rm, arr); app = fma2(tp, pm, app); arp = fma2(tr, pm, arp);
                }
                rl = rn; pl = pn;
            }
            const int wi = (sw * 8 + rloc) * 32 + pair;
            hA[wi] = make_ulonglong2(ar, ap);
            hB[wi] = make_ulonglong2(arr, app);
            hC[wi] = arp;
        }
        __syncthreads();

        // ---- vertical + pointwise for output group gv = i - LAG ----
        const int gv = i - LAG;
        if (gv >= 0) {
            const int y = 8 * gv + rloc;
            if (y < HO) {
                const int byg = sv * 8 + rloc;
                u64 a1 = 0, a2 = 0, b1 = 0, b2 = 0, cc = 0;
                #pragma unroll
                for (int t = 0; t < N; t++) {
                    int idx = byg + t;
                    if (idx >= RR) idx -= RR;
                    u64 w = ww2[(t <= HLF) ? t : (N - 1 - t)];
                    ulonglong2 A = hA[idx * 32 + pair];
                    ulonglong2 B = hB[idx * 32 + pair];
                    u64        C = hC[idx * 32 + pair];
                    a1 = fma2(w, A.x, a1);
                    a2 = fma2(w, A.y, a2);
                    b1 = fma2(w, B.x, b1);
                    b2 = fma2(w, B.y, b2);
                    cc = fma2(w, C,   cc);
                }
                float m1[2], m2[2], rr[2], pp[2], rp[2];
                upk(a1, m1[0], m1[1]);
                upk(a2, m2[0], m2[1]);
                upk(b1, rr[0], rr[1]);
                upk(b2, pp[0], pp[1]);
                upk(cc, rp[0], rp[1]);
                const int oxb = x0 + 2 * pair;
                #pragma unroll
                for (int c = 0; c < 2; c++) {
                    if (oxb + c >= WO) continue;
                    float sGT = fmaxf(rr[c] - m1[c] * m1[c], 0.0f);
                    float sP  = fmaxf(pp[c] - m2[c] * m2[c], 0.0f);
                    float sGP = rp[c] - m1[c] * m2[c];
                    // num != 0 only when all reference masks are un-triggered
                    bool cond = (sGT >= EPSV) && (sP >= EPSV) && (sGP > 0.0f);
                    float g  = cond ? __fdividef(sGP, sGT + EPSV) : 0.0f;
                    float sv_ = fmaxf(sP - g * sGP, EPSV);
                    numa += __log2f(fmaf(g * g, __fdividef(sGT, sv_ + 2.0f), 1.0f));
                    // den: sGT<EPS -> 1+sGT/2 rounds to 1.0f -> log = 0
                    dena += __log2f(fmaf(sGT, 0.5f, 1.0f));
                }
            }
        }

        if (i < GIN) { if (++sw == GR) sw = 0; }
        if (gv >= 0) { if (++sv == GR) sv = 0; }
    }

    // ---- block reduction -> per-channel atomics ----
    #pragma unroll
    for (int o = 16; o > 0; o >>= 1) {
        numa += __shfl_down_sync(0xFFFFFFFFu, numa, o);
        dena += __shfl_down_sync(0xFFFFFFFFu, dena, o);
    }
    if ((tid & 31) == 0) {
        red[tid >> 5]       = numa;
        red[8 + (tid >> 5)] = dena;
    }
    __syncthreads();
    if (tid == 0) {
        float n = 0.f, d = 0.f;
        #pragma unroll
        for (int w = 0; w < 8; w++) { n += red[w]; d += red[8 + w]; }
        atomicAdd(&g_num[ch], n);
        atomicAdd(&g_den[ch], d);
    }
}

// ---------------- prediction term: per-image dot((x - r), W) ---------------
__global__ __launch_bounds__(1024)
void pred_kernel(const float* __restrict__ R, const float* __restrict__ X,
                 const float* __restrict__ Wl) {
    const int img = blockIdx.x;
    const int n4  = (CHN * IMH * IMW) / 4;  // 24300
    const float4* r4 = (const float4*)(R + (size_t)img * (CHN * IMH * IMW));
    const float4* x4 = (const float4*)(X + (size_t)img * (CHN * IMH * IMW));
    const float4* w4 = (const float4*)Wl;
    float acc = 0.0f;
    for (int i = threadIdx.x; i < n4; i += 1024) {
        float4 a = x4[i], b = r4[i], w = w4[i];
        acc = fmaf(a.x - b.x, w.x, acc);
        acc = fmaf(a.y - b.y, w.y, acc);
        acc = fmaf(a.z - b.z, w.z, acc);
        acc = fmaf(a.w - b.w, w.w, acc);
    }
    __shared__ float red[32];
    #pragma unroll
    for (int o = 16; o > 0; o >>= 1)
        acc += __shfl_down_sync(0xFFFFFFFFu, acc, o);
    if ((threadIdx.x & 31) == 0) red[threadIdx.x >> 5] = acc;
    __syncthreads();
    if (threadIdx.x < 32) {
        float v = red[threadIdx.x];
        #pragma unroll
        for (int o = 16; o > 0; o >>= 1)
            v += __shfl_down_sync(0xFFFFFFFFu, v, o);
        if (threadIdx.x == 0) g_dot[img] = v;
    }
}

// ---------------- final: assemble the 3 scalars ----------------------------
__global__ void final_kernel(float* __restrict__ out) {
    const int t = threadIdx.x;  // 128 threads, one per image
    float vif = 0.0f;
    #pragma unroll
    for (int c = 0; c < CHN; c++) {
        int ch = t * CHN + c;
        vif += g_num[ch] / g_den[ch];
    }
    vif *= (1.0f / CHN);
    float rl = 1.0f - vif;
    float d  = g_dot[t];
    float pl = d * d;

    __shared__ float red[8];
    #pragma unroll
    for (int o = 16; o > 0; o >>= 1) {
        rl += __shfl_down_sync(0xFFFFFFFFu, rl, o);
        pl += __shfl_down_sync(0xFFFFFFFFu, pl, o);
    }
    if ((t & 31) == 0) {
        red[t >> 5]       = rl;
        red[4 + (t >> 5)] = pl;
    }
    __syncthreads();
    if (t == 0) {
        float rls = 0.f, pls = 0.f;
        #pragma unroll
        for (int w = 0; w < 4; w++) { rls += red[w]; pls += red[4 + w]; }
        rls *= (1.0f / BATCH);
        pls *= (1.0f / BATCH);
        out[0] = pls + rls;  // loss
        out[1] = rls;        // recons_loss
        out[2] = pls;        // prediction_loss
    }
}

// ---------------- launch ---------------------------------------------------
extern "C" void kernel_launch(void* const* d_in, const int* in_sizes, int n_in,
                              void* d_out, int out_size) {
    const float* recons = (const float*)d_in[0];
    const float* x      = (const float*)d_in[1];
    const float* Wl     = (const float*)d_in[2];
    // d_in[3] = b, cancels exactly in (pred_orig - pred_recons)
    float* out = (float*)d_out;

    init_kernel<<<1, 384>>>();

    dim3 blk(256);
    dim3 grd(4, NCH);   // 4 strips of 64 output cols x 384 channel-images
    // N, LAG, scale-index   (smem: 35.9KB / 25.2KB / 24.9KB / 24.8KB)
    vif_scale<17, 2, 0><<<grd, blk>>>(recons, x);
    vif_scale< 9, 1, 1><<<grd, blk>>>(recons, x);
    vif_scale< 5, 1, 2><<<grd, blk>>>(recons, x);
    vif_scale< 3, 1, 3><<<grd, blk>>>(recons, x);

    pred_kernel<<<BATCH, 1024>>>(recons, x, Wl);
    final_kernel<<<1, 128>>>(out);
}

// round 11
// speedup vs baseline: 1.4275x; 1.4023x over previous
#include <cuda_runtime.h>
#include <math.h>

#define BATCH 128
#define CHN   3
#define IMH   135
#define IMW   240
#define NCH   (BATCH * CHN)
#define EPSV  1e-10f

typedef unsigned long long u64;

// ---------------- packed f32x2 helpers (sm_103a) ---------------------------
__device__ __forceinline__ u64 pk(float lo, float hi) {
    u64 r; asm("mov.b64 %0, {%1,%2};" : "=l"(r) : "f"(lo), "f"(hi)); return r;
}
__device__ __forceinline__ void upk(u64 v, float& lo, float& hi) {
    asm("mov.b64 {%0,%1}, %2;" : "=f"(lo), "=f"(hi) : "l"(v));
}
__device__ __forceinline__ u64 fma2(u64 a, u64 b, u64 c) {
    u64 d; asm("fma.rn.f32x2 %0, %1, %2, %3;" : "=l"(d) : "l"(a), "l"(b), "l"(c)); return d;
}
__device__ __forceinline__ u64 mul2(u64 a, u64 b) {
    u64 d; asm("mul.rn.f32x2 %0, %1, %2;" : "=l"(d) : "l"(a), "l"(b)); return d;
}
__device__ __forceinline__ u64 add2(u64 a, u64 b) {
    u64 d; asm("add.rn.f32x2 %0, %1, %2;" : "=l"(d) : "l"(a), "l"(b)); return d;
}
// (a.hi, b.lo) — odd-tap pair from two neighboring even pairs
__device__ __forceinline__ u64 mid(u64 a, u64 b) {
    float al, ah, bl, bh; upk(a, al, ah); upk(b, bl, bh); return pk(ah, bl);
}

// ---------------- scratch (device globals — no allocation) ----------------
__device__ float g_num[NCH];
__device__ float g_den[NCH];
__device__ float g_dot[BATCH];
__device__ u64   g_w2[4][9];   // packed (w,w); symmetric half j=0..(N-1)/2

// ---------------- init: zero accumulators + weights every launch -----------
__global__ void init_kernel() {
    int i = threadIdx.x;
    if (i < NCH)   { g_num[i] = 0.0f; g_den[i] = 0.0f; }
    if (i < BATCH) { g_dot[i] = 0.0f; }
    if (i == 0) {
        const int Ns[4] = {17, 9, 5, 3};
        for (int s = 0; s < 4; s++) {
            int n = Ns[s];
            float sigma  = (float)n / 5.0f;
            float inv2s2 = 1.0f / (2.0f * sigma * sigma);
            float wv[17];
            float sum = 0.0f;
            for (int j = 0; j < n; j++) {
                float d = (float)(j - n / 2);
                float v = expf(-d * d * inv2s2);
                wv[j] = v;
                sum += v;
            }
            float is = 1.0f / sum;
            for (int j = 0; j < (n + 1) / 2; j++) {
                float w = wv[j] * is;
                g_w2[s][j] = pk(w, w);
            }
        }
    }
}

// ---------------- fused separable VIF scale kernel (R7 structure) ----------
// 256 threads = 16 lanes (2 adjacent x outputs each, f32x2) x 16 y-groups.
// TX = 32 output cols, TY = 16*KY rows. Dynamic smem (may exceed 48KB).
template <int N, int KY, int SIDX>
__global__ __launch_bounds__(256)
void vif_scale(const float* __restrict__ R, const float* __restrict__ P) {
    constexpr int TY = 16 * KY;
    constexpr int IH = TY + N - 1;
    constexpr int IW = 32 + N - 1;       // even (N odd) -> LDS.64 aligned
    constexpr int HO = IMH - N + 1;
    constexpr int WO = IMW - N + 1;
    constexpr int HLF = (N - 1) / 2;
    constexpr int NH = (N + 1) / 2;

    extern __shared__ __align__(16) char SM[];
    float*      s_r = (float*)SM;
    float*      s_p = s_r + IH * IW;
    ulonglong2* hA  = (ulonglong2*)(SM + 8 * IH * IW);  // (hr2, hp2)
    ulonglong2* hB  = hA + IH * 16;                     // (hrr2, hpp2)
    u64*        hC  = (u64*)(hB + IH * 16);             // hrp2
    float*      red = (float*)(hC + IH * 16);           // 16 floats

    const int tid  = threadIdx.x;
    const int lane = tid & 15;
    const int yg   = tid >> 4;
    const int ch   = blockIdx.z;
    const int ox0  = blockIdx.x * 32;
    const int oy0  = blockIdx.y * TY;

    u64 ww[NH];
    #pragma unroll
    for (int j = 0; j < NH; j++) ww[j] = g_w2[SIDX][j];

    // ---- load tile (zero-fill outside image; invalid outputs masked) ----
    const float* __restrict__ r = R + (size_t)ch * (IMH * IMW);
    const float* __restrict__ p = P + (size_t)ch * (IMH * IMW);
    for (int idx = tid; idx < IH * IW; idx += 256) {
        int iy = idx / IW, ix = idx - iy * IW;
        int gy = oy0 + iy, gx = ox0 + ix;
        float rv = 0.0f, pv = 0.0f;
        if (gy < IMH && gx < IMW) {
            int o = gy * IMW + gx;
            rv = r[o]; pv = p[o];
        }
        s_r[idx] = rv; s_p[idx] = pv;
    }
    __syncthreads();

    // ---- horizontal pass: 5 packed windowed sums for 2 adjacent outputs ----
    for (int row = yg; row < IH; row += 16) {
        const int base = row * IW + 2 * lane;   // even -> LDS.64 aligned
        u64 rl = *(const u64*)&s_r[base];
        u64 pl = *(const u64*)&s_p[base];
        // tap 0 initializes (no add-into-zero)
        u64 ar, ap, arr, app, arp;
        {
            u64 w  = ww[0];
            u64 tr = mul2(w, rl), tp = mul2(w, pl);
            ar = tr; ap = tp;
            arr = mul2(tr, rl); app = mul2(tp, pl); arp = mul2(tr, pl);
        }
        #pragma unroll
        for (int j2 = 2; j2 < N; j2 += 2) {
            u64 rn = *(const u64*)&s_r[base + j2];
            u64 pn = *(const u64*)&s_p[base + j2];
            {   // even tap j2
                u64 w  = ww[(j2 <= HLF) ? j2 : (N - 1 - j2)];
                u64 tr = mul2(w, rn), tp = mul2(w, pn);
                ar = add2(ar, tr); ap = add2(ap, tp);
                arr = fma2(tr, rn, arr); app = fma2(tp, pn, app); arp = fma2(tr, pn, arp);
            }
            {   // odd tap j2-1, pair built from neighbor halves
                int jm = j2 - 1;
                u64 w  = ww[(jm <= HLF) ? jm : (N - 1 - jm)];
                u64 rm = mid(rl, rn), pm = mid(pl, pn);
                u64 tr = mul2(w, rm), tp = mul2(w, pm);
                ar = add2(ar, tr); ap = add2(ap, tp);
                arr = fma2(tr, rm, arr); app = fma2(tp, pm, app); arp = fma2(tr, pm, arp);
            }
            rl = rn; pl = pn;
        }
        hA[row * 16 + lane] = make_ulonglong2(ar, ap);
        hB[row * 16 + lane] = make_ulonglong2(arr, app);
        hC[row * 16 + lane] = arp;
    }
    __syncthreads();

    // ---- vertical pass: KY packed output-rows per thread ----
    const int y0 = yg * KY;
    u64 am1[KY], am2[KY], vrr[KY], vpp[KY], vrp[KY];
    #pragma unroll
    for (int k = 0; k < KY; k++) { am1[k] = 0; am2[k] = 0; vrr[k] = 0; vpp[k] = 0; vrp[k] = 0; }

    #pragma unroll
    for (int t = 0; t < KY + N - 1; t++) {
        int row = y0 + t;
        ulonglong2 A = hA[row * 16 + lane];
        ulonglong2 B = hB[row * 16 + lane];
        u64        C = hC[row * 16 + lane];
        #pragma unroll
        for (int k = 0; k < KY; k++) {
            int j = t - k;
            if (j >= 0 && j < N) {           // static in unrolled loops
                u64 w = ww[(j <= HLF) ? j : (N - 1 - j)];
                am1[k] = fma2(w, A.x, am1[k]);
                am2[k] = fma2(w, A.y, am2[k]);
                vrr[k] = fma2(w, B.x, vrr[k]);
                vpp[k] = fma2(w, B.y, vpp[k]);
                vrp[k] = fma2(w, C,   vrp[k]);
            }
        }
    }

    // ---- pointwise (collapsed masks; batched logs: terms in [1, ~1.13]
    //      by Cauchy-Schwarz g^2*sGT <= sP <= 0.25, so a product of up to
    //      2*KY terms is exact enough; masked/skipped terms are exactly 1) --
    float prodN = 1.0f, prodD = 1.0f;
    const int oxb = ox0 + 2 * lane;
    #pragma unroll
    for (int k = 0; k < KY; k++) {
        if (oy0 + y0 + k >= HO) continue;
        float m1[2], m2[2], rr[2], pp[2], rp[2];
        upk(am1[k], m1[0], m1[1]);
        upk(am2[k], m2[0], m2[1]);
        upk(vrr[k], rr[0], rr[1]);
        upk(vpp[k], pp[0], pp[1]);
        upk(vrp[k], rp[0], rp[1]);
        #pragma unroll
        for (int c = 0; c < 2; c++) {
            if (oxb + c >= WO) continue;
            float sGT = fmaxf(rr[c] - m1[c] * m1[c], 0.0f);
            float sP  = fmaxf(pp[c] - m2[c] * m2[c], 0.0f);
            float sGP = rp[c] - m1[c] * m2[c];
            // num != 0 only when all reference masks are un-triggered:
            bool cond = (sGT >= EPSV) && (sP >= EPSV) && (sGP > 0.0f);
            float g  = cond ? __fdividef(sGP, sGT + EPSV) : 0.0f;
            float sv = fmaxf(sP - g * sGP, EPSV);
            prodN *= fmaf(g * g, __fdividef(sGT, sv + 2.0f), 1.0f);
            // den: sGT<EPS -> 1+sGT/2 rounds to 1.0f -> contributes 0, same
            prodD *= fmaf(sGT, 0.5f, 1.0f);
        }
    }
    float numa = __log2f(prodN);   // log10 scale cancels in num/den ratio
    float dena = __log2f(prodD);

    // ---- reduction -> per-channel atomics ----
    #pragma unroll
    for (int o = 16; o > 0; o >>= 1) {
        numa += __shfl_down_sync(0xFFFFFFFFu, numa, o);
        dena += __shfl_down_sync(0xFFFFFFFFu, dena, o);
    }
    if ((tid & 31) == 0) {
        red[tid >> 5]       = numa;
        red[8 + (tid >> 5)] = dena;
    }
    __syncthreads();
    if (tid == 0) {
        float n = 0.f, d = 0.f;
        #pragma unroll
        for (int w = 0; w < 8; w++) { n += red[w]; d += red[8 + w]; }
        atomicAdd(&g_num[ch], n);
        atomicAdd(&g_den[ch], d);
    }
}

// ---------------- prediction term: per-image dot((x - r), W) ---------------
__global__ __launch_bounds__(1024)
void pred_kernel(const float* __restrict__ R, const float* __restrict__ X,
                 const float* __restrict__ Wl) {
    const int img = blockIdx.x;
    const int n4  = (CHN * IMH * IMW) / 4;  // 24300
    const float4* r4 = (const float4*)(R + (size_t)img * (CHN * IMH * IMW));
    const float4* x4 = (const float4*)(X + (size_t)img * (CHN * IMH * IMW));
    const float4* w4 = (const float4*)Wl;
    float acc = 0.0f;
    for (int i = threadIdx.x; i < n4; i += 1024) {
        float4 a = x4[i], b = r4[i], w = w4[i];
        acc = fmaf(a.x - b.x, w.x, acc);
        acc = fmaf(a.y - b.y, w.y, acc);
        acc = fmaf(a.z - b.z, w.z, acc);
        acc = fmaf(a.w - b.w, w.w, acc);
    }
    __shared__ float red[32];
    #pragma unroll
    for (int o = 16; o > 0; o >>= 1)
        acc += __shfl_down_sync(0xFFFFFFFFu, acc, o);
    if ((threadIdx.x & 31) == 0) red[threadIdx.x >> 5] = acc;
    __syncthreads();
    if (threadIdx.x < 32) {
        float v = red[threadIdx.x];
        #pragma unroll
        for (int o = 16; o > 0; o >>= 1)
            v += __shfl_down_sync(0xFFFFFFFFu, v, o);
        if (threadIdx.x == 0) g_dot[img] = v;
    }
}

// ---------------- final: assemble the 3 scalars ----------------------------
__global__ void final_kernel(float* __restrict__ out) {
    const int t = threadIdx.x;  // 128 threads, one per image
    float vif = 0.0f;
    #pragma unroll
    for (int c = 0; c < CHN; c++) {
        int ch = t * CHN + c;
        vif += g_num[ch] / g_den[ch];
    }
    vif *= (1.0f / CHN);
    float rl = 1.0f - vif;
    float d  = g_dot[t];
    float pl = d * d;

    __shared__ float red[8];
    #pragma unroll
    for (int o = 16; o > 0; o >>= 1) {
        rl += __shfl_down_sync(0xFFFFFFFFu, rl, o);
        pl += __shfl_down_sync(0xFFFFFFFFu, pl, o);
    }
    if ((t & 31) == 0) {
        red[t >> 5]       = rl;
        red[4 + (t >> 5)] = pl;
    }
    __syncthreads();
    if (t == 0) {
        float rls = 0.f, pls = 0.f;
        #pragma unroll
        for (int w = 0; w < 4; w++) { rls += red[w]; pls += red[4 + w]; }
        rls *= (1.0f / BATCH);
        pls *= (1.0f / BATCH);
        out[0] = pls + rls;  // loss
        out[1] = rls;        // recons_loss
        out[2] = pls;        // prediction_loss
    }
}

// ---------------- launch ---------------------------------------------------
static inline int smb(int N, int KY) {
    int TY = 16 * KY, IH = TY + N - 1, IW = 32 + N - 1;
    return 8 * IH * IW + 640 * IH + 64;
}

extern "C" void kernel_launch(void* const* d_in, const int* in_sizes, int n_in,
                              void* d_out, int out_size) {
    const float* recons = (const float*)d_in[0];
    const float* x      = (const float*)d_in[1];
    const float* Wl     = (const float*)d_in[2];
    // d_in[3] = b, cancels exactly in (pred_orig - pred_recons)
    float* out = (float*)d_out;

    // opt-in to >48KB dynamic smem (attribute set, not an allocation)
    cudaFuncSetAttribute(vif_scale<17, 3, 0>,
                         cudaFuncAttributeMaxDynamicSharedMemorySize, smb(17, 3));
    cudaFuncSetAttribute(vif_scale< 9, 3, 1>,
                         cudaFuncAttributeMaxDynamicSharedMemorySize, smb(9, 3));
    cudaFuncSetAttribute(vif_scale< 5, 3, 2>,
                         cudaFuncAttributeMaxDynamicSharedMemorySize, smb(5, 3));
    cudaFuncSetAttribute(vif_scale< 3, 3, 3>,
                         cudaFuncAttributeMaxDynamicSharedMemorySize, smb(3, 3));

    init_kernel<<<1, 384>>>();

    dim3 blk(256);
    // N=17: out 119x224, TY=48 -> grid 7x3   (smem 65600, 3 blk/SM)
    vif_scale<17, 3, 0><<<dim3(7, 3, NCH), blk, smb(17, 3)>>>(recons, x);
    // N=9:  out 127x232, TY=48 -> grid 8x3   (smem 53824, 4 blk/SM)
    vif_scale< 9, 3, 1><<<dim3(8, 3, NCH), blk, smb(9, 3)>>>(recons, x);
    // N=5:  out 131x236, TY=48 -> grid 8x3   (smem 48320, 4 blk/SM)
    vif_scale< 5, 3, 2><<<dim3(8, 3, NCH), blk, smb(5, 3)>>>(recons, x);
    // N=3:  out 133x238, TY=48 -> grid 8x3   (smem 45664, 4 blk/SM)
    vif_scale< 3, 3, 3><<<dim3(8, 3, NCH), blk, smb(3, 3)>>>(recons, x);

    pred_kernel<<<BATCH, 1024>>>(recons, x, Wl);
    final_kernel<<<1, 128>>>(out);
}

// round 12
// speedup vs baseline: 1.7914x; 1.2550x over previous
#include <cuda_runtime.h>
#include <math.h>

#define BATCH 128
#define CHN   3
#define IMH   135
#define IMW   240
#define NCH   (BATCH * CHN)
#define EPSV  1e-10f

typedef unsigned long long u64;

// ---------------- packed f32x2 helpers (sm_103a) ---------------------------
__device__ __forceinline__ u64 pk(float lo, float hi) {
    u64 r; asm("mov.b64 %0, {%1,%2};" : "=l"(r) : "f"(lo), "f"(hi)); return r;
}
__device__ __forceinline__ void upk(u64 v, float& lo, float& hi) {
    asm("mov.b64 {%0,%1}, %2;" : "=f"(lo), "=f"(hi) : "l"(v));
}
__device__ __forceinline__ u64 fma2(u64 a, u64 b, u64 c) {
    u64 d; asm("fma.rn.f32x2 %0, %1, %2, %3;" : "=l"(d) : "l"(a), "l"(b), "l"(c)); return d;
}
__device__ __forceinline__ u64 mul2(u64 a, u64 b) {
    u64 d; asm("mul.rn.f32x2 %0, %1, %2;" : "=l"(d) : "l"(a), "l"(b)); return d;
}
__device__ __forceinline__ u64 add2(u64 a, u64 b) {
    u64 d; asm("add.rn.f32x2 %0, %1, %2;" : "=l"(d) : "l"(a), "l"(b)); return d;
}
// (a.hi, b.lo) — odd-tap pair from two neighboring even pairs
__device__ __forceinline__ u64 mid(u64 a, u64 b) {
    float al, ah, bl, bh; upk(a, al, ah); upk(b, bl, bh); return pk(ah, bl);
}

// ---------------- scratch (device globals — no allocation) ----------------
__device__ float g_num[NCH];
__device__ float g_den[NCH];
__device__ float g_dot[BATCH];
__device__ u64   g_w2[4][9];   // packed (w,w); symmetric half j=0..(N-1)/2

// ---------------- init: zero accumulators + weights every launch -----------
__global__ void init_kernel() {
    int i = threadIdx.x;
    if (i < NCH)   { g_num[i] = 0.0f; g_den[i] = 0.0f; }
    if (i < BATCH) { g_dot[i] = 0.0f; }
    if (i == 0) {
        const int Ns[4] = {17, 9, 5, 3};
        for (int s = 0; s < 4; s++) {
            int n = Ns[s];
            float sigma  = (float)n / 5.0f;
            float inv2s2 = 1.0f / (2.0f * sigma * sigma);
            float wv[17];
            float sum = 0.0f;
            for (int j = 0; j < n; j++) {
                float d = (float)(j - n / 2);
                float v = expf(-d * d * inv2s2);
                wv[j] = v;
                sum += v;
            }
            float is = 1.0f / sum;
            for (int j = 0; j < (n + 1) / 2; j++) {
                float w = wv[j] * is;
                g_w2[s][j] = pk(w, w);
            }
        }
    }
}

// ---------------- fused separable VIF scale kernel -------------------------
// 256 threads = 16 lanes (2 adjacent x outputs each, f32x2) x 16 y-groups.
// TX = 32 output cols, TY = 16*KY rows. Inputs staged interleaved as
// float4 (r0,r1,p0,p1) so horizontal uses one LDS.128 per even tap.
template <int N, int KY, int SIDX>
__global__ __launch_bounds__(256)
void vif_scale(const float* __restrict__ R, const float* __restrict__ P) {
    constexpr int TY  = 16 * KY;
    constexpr int IH  = TY + N - 1;
    constexpr int IW  = 32 + N - 1;      // even (N odd)
    constexpr int IWH = IW / 2;          // float4 pair-columns per row
    constexpr int HO  = IMH - N + 1;
    constexpr int WO  = IMW - N + 1;
    constexpr int HLF = (N - 1) / 2;
    constexpr int NH  = (N + 1) / 2;

    extern __shared__ __align__(16) char SM[];
    float4*     s4  = (float4*)SM;                       // IH*IWH
    ulonglong2* hA  = (ulonglong2*)(SM + 16 * IH * IWH); // (hr2, hp2)
    ulonglong2* hB  = hA + IH * 16;                      // (hrr2, hpp2)
    u64*        hC  = (u64*)(hB + IH * 16);              // hrp2
    float*      red = (float*)(hC + IH * 16);            // 16 floats

    const int tid  = threadIdx.x;
    const int lane = tid & 15;
    const int yg   = tid >> 4;
    const int ch   = blockIdx.z;
    const int ox0  = blockIdx.x * 32;
    const int oy0  = blockIdx.y * TY;

    u64 ww[NH];
    #pragma unroll
    for (int j = 0; j < NH; j++) ww[j] = g_w2[SIDX][j];

    // ---- stage tile interleaved (r0,r1,p0,p1); zero-fill outside image ----
    const float* __restrict__ r = R + (size_t)ch * (IMH * IMW);
    const float* __restrict__ p = P + (size_t)ch * (IMH * IMW);
    for (int idx = tid; idx < IH * IWH; idx += 256) {
        int row = idx / IWH, c2 = idx - row * IWH;
        int gy = oy0 + row, gx = ox0 + 2 * c2;   // gx even, u64-aligned
        u64 rv = 0ull, pv = 0ull;
        if (gy < IMH && gx < IMW) {
            int o = gy * IMW + gx;
            rv = *(const u64*)&r[o];
            pv = *(const u64*)&p[o];
        }
        float4 st;
        upk(rv, st.x, st.y);
        upk(pv, st.z, st.w);
        s4[idx] = st;
    }
    __syncthreads();

    // ---- horizontal pass: 5 packed windowed sums for 2 adjacent outputs ----
    for (int row = yg; row < IH; row += 16) {
        const int base2 = row * IWH + lane;
        float4 F = s4[base2];
        u64 rl = pk(F.x, F.y);
        u64 pl = pk(F.z, F.w);
        // tap 0 initializes (no add-into-zero)
        u64 ar, ap, arr, app, arp;
        {
            u64 w  = ww[0];
            u64 tr = mul2(w, rl), tp = mul2(w, pl);
            ar = tr; ap = tp;
            arr = mul2(tr, rl); app = mul2(tp, pl); arp = mul2(tr, pl);
        }
        #pragma unroll
        for (int j2 = 2; j2 < N; j2 += 2) {
            float4 G = s4[base2 + j2 / 2];       // one LDS.128 per tap-pair
            u64 rn = pk(G.x, G.y);
            u64 pn = pk(G.z, G.w);
            {   // even tap j2
                u64 w  = ww[(j2 <= HLF) ? j2 : (N - 1 - j2)];
                u64 tr = mul2(w, rn), tp = mul2(w, pn);
                ar = add2(ar, tr); ap = add2(ap, tp);
                arr = fma2(tr, rn, arr); app = fma2(tp, pn, app); arp = fma2(tr, pn, arp);
            }
            {   // odd tap j2-1, pair built from neighbor halves
                int jm = j2 - 1;
                u64 w  = ww[(jm <= HLF) ? jm : (N - 1 - jm)];
                u64 rm = mid(rl, rn), pm = mid(pl, pn);
                u64 tr = mul2(w, rm), tp = mul2(w, pm);
                ar = add2(ar, tr); ap = add2(ap, tp);
                arr = fma2(tr, rm, arr); app = fma2(tp, pm, app); arp = fma2(tr, pm, arp);
            }
            rl = rn; pl = pn;
        }
        hA[row * 16 + lane] = make_ulonglong2(ar, ap);
        hB[row * 16 + lane] = make_ulonglong2(arr, app);
        hC[row * 16 + lane] = arp;
    }
    __syncthreads();

    // ---- vertical pass: KY packed output-rows per thread ----
    const int y0 = yg * KY;
    u64 am1[KY], am2[KY], vrr[KY], vpp[KY], vrp[KY];
    #pragma unroll
    for (int k = 0; k < KY; k++) { am1[k] = 0; am2[k] = 0; vrr[k] = 0; vpp[k] = 0; vrp[k] = 0; }

    #pragma unroll
    for (int t = 0; t < KY + N - 1; t++) {
        int row = y0 + t;
        ulonglong2 A = hA[row * 16 + lane];
        ulonglong2 B = hB[row * 16 + lane];
        u64        C = hC[row * 16 + lane];
        #pragma unroll
        for (int k = 0; k < KY; k++) {
            int j = t - k;
            if (j >= 0 && j < N) {           // static in unrolled loops
                u64 w = ww[(j <= HLF) ? j : (N - 1 - j)];
                am1[k] = fma2(w, A.x, am1[k]);
                am2[k] = fma2(w, A.y, am2[k]);
                vrr[k] = fma2(w, B.x, vrr[k]);
                vpp[k] = fma2(w, B.y, vpp[k]);
                vrp[k] = fma2(w, C,   vrp[k]);
            }
        }
    }

    // ---- pointwise (collapsed masks; batched logs: each term in [1,~1.13]
    //      by Cauchy-Schwarz, masked/skipped terms are exactly 1) ----------
    float prodN = 1.0f, prodD = 1.0f;
    const int oxb = ox0 + 2 * lane;
    #pragma unroll
    for (int k = 0; k < KY; k++) {
        if (oy0 + y0 + k >= HO) continue;
        float m1[2], m2[2], rr[2], pp[2], rp[2];
        upk(am1[k], m1[0], m1[1]);
        upk(am2[k], m2[0], m2[1]);
        upk(vrr[k], rr[0], rr[1]);
        upk(vpp[k], pp[0], pp[1]);
        upk(vrp[k], rp[0], rp[1]);
        #pragma unroll
        for (int c = 0; c < 2; c++) {
            if (oxb + c >= WO) continue;
            float sGT = fmaxf(rr[c] - m1[c] * m1[c], 0.0f);
            float sP  = fmaxf(pp[c] - m2[c] * m2[c], 0.0f);
            float sGP = rp[c] - m1[c] * m2[c];
            // num != 0 only when all reference masks are un-triggered:
            bool cond = (sGT >= EPSV) && (sP >= EPSV) && (sGP > 0.0f);
            float g  = cond ? __fdividef(sGP, sGT + EPSV) : 0.0f;
            float sv = fmaxf(sP - g * sGP, EPSV);
            prodN *= fmaf(g * g, __fdividef(sGT, sv + 2.0f), 1.0f);
            // den: sGT<EPS -> 1+sGT/2 rounds to 1.0f -> contributes 0, same
            prodD *= fmaf(sGT, 0.5f, 1.0f);
        }
    }
    float numa = __log2f(prodN);   // log10 scale cancels in num/den ratio
    float dena = __log2f(prodD);

    // ---- reduction -> per-channel atomics ----
    #pragma unroll
    for (int o = 16; o > 0; o >>= 1) {
        numa += __shfl_down_sync(0xFFFFFFFFu, numa, o);
        dena += __shfl_down_sync(0xFFFFFFFFu, dena, o);
    }
    if ((tid & 31) == 0) {
        red[tid >> 5]       = numa;
        red[8 + (tid >> 5)] = dena;
    }
    __syncthreads();
    if (tid == 0) {
        float n = 0.f, d = 0.f;
        #pragma unroll
        for (int w = 0; w < 8; w++) { n += red[w]; d += red[8 + w]; }
        atomicAdd(&g_num[ch], n);
        atomicAdd(&g_den[ch], d);
    }
}

// ---------------- prediction term: per-image dot((x - r), W) ---------------
__global__ __launch_bounds__(1024)
void pred_kernel(const float* __restrict__ R, const float* __restrict__ X,
                 const float* __restrict__ Wl) {
    const int img = blockIdx.x;
    const int n4  = (CHN * IMH * IMW) / 4;  // 24300
    const float4* r4 = (const float4*)(R + (size_t)img * (CHN * IMH * IMW));
    const float4* x4 = (const float4*)(X + (size_t)img * (CHN * IMH * IMW));
    const float4* w4 = (const float4*)Wl;
    float acc = 0.0f;
    for (int i = threadIdx.x; i < n4; i += 1024) {
        float4 a = x4[i], b = r4[i], w = w4[i];
        acc = fmaf(a.x - b.x, w.x, acc);
        acc = fmaf(a.y - b.y, w.y, acc);
        acc = fmaf(a.z - b.z, w.z, acc);
        acc = fmaf(a.w - b.w, w.w, acc);
    }
    __shared__ float red[32];
    #pragma unroll
    for (int o = 16; o > 0; o >>= 1)
        acc += __shfl_down_sync(0xFFFFFFFFu, acc, o);
    if ((threadIdx.x & 31) == 0) red[threadIdx.x >> 5] = acc;
    __syncthreads();
    if (threadIdx.x < 32) {
        float v = red[threadIdx.x];
        #pragma unroll
        for (int o = 16; o > 0; o >>= 1)
            v += __shfl_down_sync(0xFFFFFFFFu, v, o);
        if (threadIdx.x == 0) g_dot[img] = v;
    }
}

// ---------------- final: assemble the 3 scalars ----------------------------
__global__ void final_kernel(float* __restrict__ out) {
    const int t = threadIdx.x;  // 128 threads, one per image
    float vif = 0.0f;
    #pragma unroll
    for (int c = 0; c < CHN; c++) {
        int ch = t * CHN + c;
        vif += g_num[ch] / g_den[ch];
    }
    vif *= (1.0f / CHN);
    float rl = 1.0f - vif;
    float d  = g_dot[t];
    float pl = d * d;

    __shared__ float red[8];
    #pragma unroll
    for (int o = 16; o > 0; o >>= 1) {
        rl += __shfl_down_sync(0xFFFFFFFFu, rl, o);
        pl += __shfl_down_sync(0xFFFFFFFFu, pl, o);
    }
    if ((t & 31) == 0) {
        red[t >> 5]       = rl;
        red[4 + (t >> 5)] = pl;
    }
    __syncthreads();
    if (t == 0) {
        float rls = 0.f, pls = 0.f;
        #pragma unroll
        for (int w = 0; w < 4; w++) { rls += red[w]; pls += red[4 + w]; }
        rls *= (1.0f / BATCH);
        pls *= (1.0f / BATCH);
        out[0] = pls + rls;  // loss
        out[1] = rls;        // recons_loss
        out[2] = pls;        // prediction_loss
    }
}

// ---------------- launch ---------------------------------------------------
static inline int smb(int N, int KY) {
    int TY = 16 * KY, IH = TY + N - 1, IW = 32 + N - 1;
    return 8 * IH * IW + 640 * IH + 64;
}

extern "C" void kernel_launch(void* const* d_in, const int* in_sizes, int n_in,
                              void* d_out, int out_size) {
    const float* recons = (const float*)d_in[0];
    const float* x      = (const float*)d_in[1];
    const float* Wl     = (const float*)d_in[2];
    // d_in[3] = b, cancels exactly in (pred_orig - pred_recons)
    float* out = (float*)d_out;

    // opt-in to >48KB dynamic smem (attribute set, not an allocation)
    cudaFuncSetAttribute(vif_scale<17, 3, 0>,
                         cudaFuncAttributeMaxDynamicSharedMemorySize, smb(17, 3));
    cudaFuncSetAttribute(vif_scale< 9, 2, 1>,
                         cudaFuncAttributeMaxDynamicSharedMemorySize, smb(9, 2));
    cudaFuncSetAttribute(vif_scale< 5, 2, 2>,
                         cudaFuncAttributeMaxDynamicSharedMemorySize, smb(5, 2));
    cudaFuncSetAttribute(vif_scale< 3, 2, 3>,
                         cudaFuncAttributeMaxDynamicSharedMemorySize, smb(3, 2));

    init_kernel<<<1, 384>>>();

    dim3 blk(256);
    // N=17: LDS-byte-bound -> KY=3 (min vertical bytes). out 119x224,
    //       TY=48 -> grid 7x3, smem 65600, 3 blk/SM
    vif_scale<17, 3, 0><<<dim3(7, 3, NCH), blk, smb(17, 3)>>>(recons, x);
    // N=9: latency-bound -> KY=2 for warps. out 127x232, TY=32 -> grid 8x4,
    //      smem 38464, 5 blk/SM
    vif_scale< 9, 2, 1><<<dim3(8, 4, NCH), blk, smb(9, 2)>>>(recons, x);
    // N=5: KY=2. out 131x236, TY=32 -> grid 8x5, smem 33472, 5-6 blk/SM
    vif_scale< 5, 2, 2><<<dim3(8, 5, NCH), blk, smb(5, 2)>>>(recons, x);
    // N=3: KY=2. out 133x238, TY=32 -> grid 8x5, smem 31072, 6 blk/SM
    vif_scale< 3, 2, 3><<<dim3(8, 5, NCH), blk, smb(3, 2)>>>(recons, x);

    pred_kernel<<<BATCH, 1024>>>(recons, x, Wl);
    final_kernel<<<1, 128>>>(out);
}

// round 13
// speedup vs baseline: 1.7916x; 1.0001x over previous
#include <cuda_runtime.h>
#include <math.h>

#define BATCH 128
#define CHN   3
#define IMH   135
#define IMW   240
#define NCH   (BATCH * CHN)
#define EPSV  1e-10f

typedef unsigned long long u64;

// ---------------- packed f32x2 helpers (sm_103a) ---------------------------
__device__ __forceinline__ u64 pk(float lo, float hi) {
    u64 r; asm("mov.b64 %0, {%1,%2};" : "=l"(r) : "f"(lo), "f"(hi)); return r;
}
__device__ __forceinline__ void upk(u64 v, float& lo, float& hi) {
    asm("mov.b64 {%0,%1}, %2;" : "=f"(lo), "=f"(hi) : "l"(v));
}
__device__ __forceinline__ u64 fma2(u64 a, u64 b, u64 c) {
    u64 d; asm("fma.rn.f32x2 %0, %1, %2, %3;" : "=l"(d) : "l"(a), "l"(b), "l"(c)); return d;
}
__device__ __forceinline__ u64 mul2(u64 a, u64 b) {
    u64 d; asm("mul.rn.f32x2 %0, %1, %2;" : "=l"(d) : "l"(a), "l"(b)); return d;
}
__device__ __forceinline__ u64 add2(u64 a, u64 b) {
    u64 d; asm("add.rn.f32x2 %0, %1, %2;" : "=l"(d) : "l"(a), "l"(b)); return d;
}
// (a.hi, b.lo) — odd-tap pair from two neighboring even pairs
__device__ __forceinline__ u64 mid(u64 a, u64 b) {
    float al, ah, bl, bh; upk(a, al, ah); upk(b, bl, bh); return pk(ah, bl);
}

// ---------------- scratch (device globals — no allocation) ----------------
__device__ float g_num[NCH];
__device__ float g_den[NCH];
__device__ float g_dot[BATCH];
__device__ u64   g_w2[4][9];   // packed (w,w); symmetric half j=0..(N-1)/2

// ---------------- init: zero accumulators + weights every launch -----------
__global__ void init_kernel() {
    int i = threadIdx.x;
    if (i < NCH)   { g_num[i] = 0.0f; g_den[i] = 0.0f; }
    if (i < BATCH) { g_dot[i] = 0.0f; }
    if (i == 0) {
        const int Ns[4] = {17, 9, 5, 3};
        for (int s = 0; s < 4; s++) {
            int n = Ns[s];
            float sigma  = (float)n / 5.0f;
            float inv2s2 = 1.0f / (2.0f * sigma * sigma);
            float wv[17];
            float sum = 0.0f;
            for (int j = 0; j < n; j++) {
                float d = (float)(j - n / 2);
                float v = expf(-d * d * inv2s2);
                wv[j] = v;
                sum += v;
            }
            float is = 1.0f / sum;
            for (int j = 0; j < (n + 1) / 2; j++) {
                float w = wv[j] * is;
                g_w2[s][j] = pk(w, w);
            }
        }
    }
}

// ---------------- fused separable VIF scale kernel -------------------------
// 384 threads = 16 lanes (2 adjacent x outputs each, f32x2) x 24 y-groups,
// KY=2 -> TY=48 output rows, TX=32 output cols per block. Inputs staged
// interleaved as float4 (r0,r1,p0,p1): one LDS.128 per horizontal tap-pair.
template <int N, int SIDX>
__global__ __launch_bounds__(384)
void vif_scale(const float* __restrict__ R, const float* __restrict__ P) {
    constexpr int KY  = 2;
    constexpr int NYG = 24;              // y-groups
    constexpr int TY  = NYG * KY;        // 48
    constexpr int IH  = TY + N - 1;
    constexpr int IW  = 32 + N - 1;      // even (N odd)
    constexpr int IWH = IW / 2;          // float4 pair-columns per row
    constexpr int HO  = IMH - N + 1;
    constexpr int WO  = IMW - N + 1;
    constexpr int HLF = (N - 1) / 2;
    constexpr int NH  = (N + 1) / 2;

    extern __shared__ __align__(16) char SM[];
    float4*     s4  = (float4*)SM;                       // IH*IWH
    ulonglong2* hA  = (ulonglong2*)(SM + 16 * IH * IWH); // (hr2, hp2)
    ulonglong2* hB  = hA + IH * 16;                      // (hrr2, hpp2)
    u64*        hC  = (u64*)(hB + IH * 16);              // hrp2
    float*      red = (float*)(hC + IH * 16);            // 32 floats

    const int tid  = threadIdx.x;
    const int lane = tid & 15;
    const int yg   = tid >> 4;           // 0..23
    const int ch   = blockIdx.z;
    const int ox0  = blockIdx.x * 32;
    const int oy0  = blockIdx.y * TY;

    u64 ww[NH];
    #pragma unroll
    for (int j = 0; j < NH; j++) ww[j] = g_w2[SIDX][j];

    // ---- stage tile interleaved (r0,r1,p0,p1); zero-fill outside image ----
    const float* __restrict__ r = R + (size_t)ch * (IMH * IMW);
    const float* __restrict__ p = P + (size_t)ch * (IMH * IMW);
    for (int idx = tid; idx < IH * IWH; idx += 384) {
        int row = idx / IWH, c2 = idx - row * IWH;
        int gy = oy0 + row, gx = ox0 + 2 * c2;   // gx even, u64-aligned
        u64 rv = 0ull, pv = 0ull;
        if (gy < IMH && gx < IMW) {
            int o = gy * IMW + gx;
            rv = *(const u64*)&r[o];
            pv = *(const u64*)&p[o];
        }
        float4 st;
        upk(rv, st.x, st.y);
        upk(pv, st.z, st.w);
        s4[idx] = st;
    }
    __syncthreads();

    // ---- horizontal pass: 5 packed windowed sums for 2 adjacent outputs ----
    for (int row = yg; row < IH; row += NYG) {
        const int base2 = row * IWH + lane;
        float4 F = s4[base2];
        u64 rl = pk(F.x, F.y);
        u64 pl = pk(F.z, F.w);
        // tap 0 initializes (no add-into-zero)
        u64 ar, ap, arr, app, arp;
        {
            u64 w  = ww[0];
            u64 tr = mul2(w, rl), tp = mul2(w, pl);
            ar = tr; ap = tp;
            arr = mul2(tr, rl); app = mul2(tp, pl); arp = mul2(tr, pl);
        }
        #pragma unroll
        for (int j2 = 2; j2 < N; j2 += 2) {
            float4 G = s4[base2 + j2 / 2];       // one LDS.128 per tap-pair
            u64 rn = pk(G.x, G.y);
            u64 pn = pk(G.z, G.w);
            {   // even tap j2
                u64 w  = ww[(j2 <= HLF) ? j2 : (N - 1 - j2)];
                u64 tr = mul2(w, rn), tp = mul2(w, pn);
                ar = add2(ar, tr); ap = add2(ap, tp);
                arr = fma2(tr, rn, arr); app = fma2(tp, pn, app); arp = fma2(tr, pn, arp);
            }
            {   // odd tap j2-1, pair built from neighbor halves
                int jm = j2 - 1;
                u64 w  = ww[(jm <= HLF) ? jm : (N - 1 - jm)];
                u64 rm = mid(rl, rn), pm = mid(pl, pn);
                u64 tr = mul2(w, rm), tp = mul2(w, pm);
                ar = add2(ar, tr); ap = add2(ap, tp);
                arr = fma2(tr, rm, arr); app = fma2(tp, pm, app); arp = fma2(tr, pm, arp);
            }
            rl = rn; pl = pn;
        }
        hA[row * 16 + lane] = make_ulonglong2(ar, ap);
        hB[row * 16 + lane] = make_ulonglong2(arr, app);
        hC[row * 16 + lane] = arp;
    }
    __syncthreads();

    // ---- vertical pass: KY packed output-rows per thread ----
    const int y0 = yg * KY;
    u64 am1[KY], am2[KY], vrr[KY], vpp[KY], vrp[KY];
    #pragma unroll
    for (int k = 0; k < KY; k++) { am1[k] = 0; am2[k] = 0; vrr[k] = 0; vpp[k] = 0; vrp[k] = 0; }

    #pragma unroll
    for (int t = 0; t < KY + N - 1; t++) {
        int row = y0 + t;
        ulonglong2 A = hA[row * 16 + lane];
        ulonglong2 B = hB[row * 16 + lane];
        u64        C = hC[row * 16 + lane];
        #pragma unroll
        for (int k = 0; k < KY; k++) {
            int j = t - k;
            if (j >= 0 && j < N) {           // static in unrolled loops
                u64 w = ww[(j <= HLF) ? j : (N - 1 - j)];
                am1[k] = fma2(w, A.x, am1[k]);
                am2[k] = fma2(w, A.y, am2[k]);
                vrr[k] = fma2(w, B.x, vrr[k]);
                vpp[k] = fma2(w, B.y, vpp[k]);
                vrp[k] = fma2(w, C,   vrp[k]);
            }
        }
    }

    // ---- pointwise (collapsed masks; batched logs: each term in [1,~1.13]
    //      by Cauchy-Schwarz, masked/skipped terms are exactly 1) ----------
    float prodN = 1.0f, prodD = 1.0f;
    const int oxb = ox0 + 2 * lane;
    #pragma unroll
    for (int k = 0; k < KY; k++) {
        if (oy0 + y0 + k >= HO) continue;
        float m1[2], m2[2], rr[2], pp[2], rp[2];
        upk(am1[k], m1[0], m1[1]);
        upk(am2[k], m2[0], m2[1]);
        upk(vrr[k], rr[0], rr[1]);
        upk(vpp[k], pp[0], pp[1]);
        upk(vrp[k], rp[0], rp[1]);
        #pragma unroll
        for (int c = 0; c < 2; c++) {
            if (oxb + c >= WO) continue;
            float sGT = fmaxf(rr[c] - m1[c] * m1[c], 0.0f);
            float sP  = fmaxf(pp[c] - m2[c] * m2[c], 0.0f);
            float sGP = rp[c] - m1[c] * m2[c];
            // num != 0 only when all reference masks are un-triggered:
            bool cond = (sGT >= EPSV) && (sP >= EPSV) && (sGP > 0.0f);
            float g  = cond ? __fdividef(sGP, sGT + EPSV) : 0.0f;
            float sv = fmaxf(sP - g * sGP, EPSV);
            prodN *= fmaf(g * g, __fdividef(sGT, sv + 2.0f), 1.0f);
            // den: sGT<EPS -> 1+sGT/2 rounds to 1.0f -> contributes 0, same
            prodD *= fmaf(sGT, 0.5f, 1.0f);
        }
    }
    float numa = __log2f(prodN);   // log10 scale cancels in num/den ratio
    float dena = __log2f(prodD);

    // ---- reduction (12 warps) -> per-channel atomics ----
    #pragma unroll
    for (int o = 16; o > 0; o >>= 1) {
        numa += __shfl_down_sync(0xFFFFFFFFu, numa, o);
        dena += __shfl_down_sync(0xFFFFFFFFu, dena, o);
    }
    if ((tid & 31) == 0) {
        red[tid >> 5]        = numa;
        red[16 + (tid >> 5)] = dena;
    }
    __syncthreads();
    if (tid == 0) {
        float n = 0.f, d = 0.f;
        #pragma unroll
        for (int w = 0; w < 12; w++) { n += red[w]; d += red[16 + w]; }
        atomicAdd(&g_num[ch], n);
        atomicAdd(&g_den[ch], d);
    }
}

// ---------------- prediction term: per-image dot((x - r), W) ---------------
__global__ __launch_bounds__(1024)
void pred_kernel(const float* __restrict__ R, const float* __restrict__ X,
                 const float* __restrict__ Wl) {
    const int img = blockIdx.x;
    const int n4  = (CHN * IMH * IMW) / 4;  // 24300
    const float4* r4 = (const float4*)(R + (size_t)img * (CHN * IMH * IMW));
    const float4* x4 = (const float4*)(X + (size_t)img * (CHN * IMH * IMW));
    const float4* w4 = (const float4*)Wl;
    float acc = 0.0f;
    for (int i = threadIdx.x; i < n4; i += 1024) {
        float4 a = x4[i], b = r4[i], w = w4[i];
        acc = fmaf(a.x - b.x, w.x, acc);
        acc = fmaf(a.y - b.y, w.y, acc);
        acc = fmaf(a.z - b.z, w.z, acc);
        acc = fmaf(a.w - b.w, w.w, acc);
    }
    __shared__ float red[32];
    #pragma unroll
    for (int o = 16; o > 0; o >>= 1)
        acc += __shfl_down_sync(0xFFFFFFFFu, acc, o);
    if ((threadIdx.x & 31) == 0) red[threadIdx.x >> 5] = acc;
    __syncthreads();
    if (threadIdx.x < 32) {
        float v = red[threadIdx.x];
        #pragma unroll
        for (int o = 16; o > 0; o >>= 1)
            v += __shfl_down_sync(0xFFFFFFFFu, v, o);
        if (threadIdx.x == 0) g_dot[img] = v;
    }
}

// ---------------- final: assemble the 3 scalars ----------------------------
__global__ void final_kernel(float* __restrict__ out) {
    const int t = threadIdx.x;  // 128 threads, one per image
    float vif = 0.0f;
    #pragma unroll
    for (int c = 0; c < CHN; c++) {
        int ch = t * CHN + c;
        vif += g_num[ch] / g_den[ch];
    }
    vif *= (1.0f / CHN);
    float rl = 1.0f - vif;
    float d  = g_dot[t];
    float pl = d * d;

    __shared__ float red[8];
    #pragma unroll
    for (int o = 16; o > 0; o >>= 1) {
        rl += __shfl_down_sync(0xFFFFFFFFu, rl, o);
        pl += __shfl_down_sync(0xFFFFFFFFu, pl, o);
    }
    if ((t & 31) == 0) {
        red[t >> 5]       = rl;
        red[4 + (t >> 5)] = pl;
    }
    __syncthreads();
    if (t == 0) {
        float rls = 0.f, pls = 0.f;
        #pragma unroll
        for (int w = 0; w < 4; w++) { rls += red[w]; pls += red[4 + w]; }
        rls *= (1.0f / BATCH);
        pls *= (1.0f / BATCH);
        out[0] = pls + rls;  // loss
        out[1] = rls;        // recons_loss
        out[2] = pls;        // prediction_loss
    }
}

// ---------------- launch ---------------------------------------------------
static inline int smb(int N) {
    int IH = N + 47, IW = 32 + N - 1;
    return 8 * IH * IW + 640 * IH + 128;
}

extern "C" void kernel_launch(void* const* d_in, const int* in_sizes, int n_in,
                              void* d_out, int out_size) {
    const float* recons = (const float*)d_in[0];
    const float* x      = (const float*)d_in[1];
    const float* Wl     = (const float*)d_in[2];
    // d_in[3] = b, cancels exactly in (pred_orig - pred_recons)
    float* out = (float*)d_out;

    // opt-in to >48KB dynamic smem (attribute set, not an allocation)
    cudaFuncSetAttribute(vif_scale<17, 0>,
                         cudaFuncAttributeMaxDynamicSharedMemorySize, smb(17));
    cudaFuncSetAttribute(vif_scale< 9, 1>,
                         cudaFuncAttributeMaxDynamicSharedMemorySize, smb(9));
    cudaFuncSetAttribute(vif_scale< 5, 2>,
                         cudaFuncAttributeMaxDynamicSharedMemorySize, smb(5));
    cudaFuncSetAttribute(vif_scale< 3, 3>,
                         cudaFuncAttributeMaxDynamicSharedMemorySize, smb(3));

    init_kernel<<<1, 384>>>();

    dim3 blk(384);
    // TY=48 for all scales -> grid.y = 3 (covers HO up to 144)
    // N=17: out 119x224 -> grid 7x3, smem 65664, 3 blk/SM = 36 warps (56%)
    vif_scale<17, 0><<<dim3(7, 3, NCH), blk, smb(17)>>>(recons, x);
    // N=9:  out 127x232 -> grid 8x3, smem 53888, 4 blk/SM = 48 warps (75%)
    vif_scale< 9, 1><<<dim3(8, 3, NCH), blk, smb(9)>>>(recons, x);
    // N=5:  out 131x236 -> grid 8x3, smem 48384, 4 blk/SM = 48 warps (75%)
    vif_scale< 5, 2><<<dim3(8, 3, NCH), blk, smb(5)>>>(recons, x);
    // N=3:  out 133x238 -> grid 8x3, smem 45728, 5 blk/SM = 60 warps (94%)
    vif_scale< 3, 3><<<dim3(8, 3, NCH), blk, smb(3)>>>(recons, x);

    pred_kernel<<<BATCH, 1024>>>(recons, x, Wl);
    final_kernel<<<1, 128>>>(out);
}